// round 2
// baseline (speedup 1.0000x reference)
#include <cuda_runtime.h>
#include <cstdint>

#define NC   81
#define NCP  96
#define BK   10
#define DIM  2048
#define NI   16384

#define BM    128
#define KT    32
#define PADX  132
#define PADM  100
#define NTILES (DIM / KT)
#define STAGE_FLOATS (KT * PADX + KT * PADM)     /* 7424 floats */
#define SMEM_GEMM_BYTES (2 * STAGE_FLOATS * 4)   /* 59392 B */

__device__ float g_mmean[NCP * DIM];
__device__ float g_bias[NCP];
__device__ int   g_count;

#define FMA2(d, a, b, c) asm("fma.rn.f32x2 %0, %1, %2, %3;" : "=l"(d) : "l"(a), "l"(b), "l"(c))
#define ADD2(d, a, b)    asm("add.rn.f32x2 %0, %1, %2;" : "=l"(d) : "l"(a), "l"(b))
#define PACK2(d, lo, hi) asm("mov.b64 %0, {%1, %2};" : "=l"(d) : "f"(lo), "f"(hi))
#define UNPACK2(lo, hi, v) asm("mov.b64 {%0, %1}, %2;" : "=f"(lo), "=f"(hi) : "l"(v))

// ---------------------------------------------------------------------------
// Kernel 1: per-class bank mean (+zero-pad classes 81..95) + 0.5*|mean|^2 bias
// ---------------------------------------------------------------------------
__global__ void k_mean(const float* __restrict__ mem) {
    int c = blockIdx.x;
    int tid = threadIdx.x;
    if (c == 0 && tid == 0) g_count = 0;
    if (c >= NC) {
        for (int d = tid; d < DIM; d += 256) g_mmean[c * DIM + d] = 0.f;
        if (tid == 0) g_bias[c] = 0.f;
        return;
    }
    float part = 0.f;
    for (int d = tid; d < DIM; d += 256) {
        float s = 0.f;
#pragma unroll
        for (int b = 0; b < BK; b++) s += mem[(size_t)(c * BK + b) * DIM + d];
        float m = s * (1.0f / BK);
        g_mmean[c * DIM + d] = m;
        part += m * m;
    }
#pragma unroll
    for (int o = 16; o; o >>= 1) part += __shfl_xor_sync(0xffffffffu, part, o);
    __shared__ float rb[8];
    if ((tid & 31) == 0) rb[tid >> 5] = part;
    __syncthreads();
    if (tid == 0) {
        float t = 0.f;
#pragma unroll
        for (int w = 0; w < 8; w++) t += rb[w];
        g_bias[c] = 0.5f * t;
    }
}

// ---------------------------------------------------------------------------
// Kernel 2: f32x2 GEMM (scores = bias - x.mean) + per-instance argmin.
// 128 rows x 96 cols per block (128 blocks = 1 wave). 256 threads:
// iG = tid&15 -> 8 rows (4 row-pairs packed in f32x2), cG = tid>>4 -> 6 cols.
// ---------------------------------------------------------------------------
__global__ void __launch_bounds__(256, 1) k_gemm(const float* __restrict__ X,
                                                 const int* __restrict__ labels,
                                                 float* __restrict__ out) {
    extern __shared__ float sm[];
    const int tid = threadIdx.x;
    const int iG = tid & 15;
    const int cG = tid >> 4;
    const int i0 = blockIdx.x * BM;
    const int kq = tid & 7;   // k-quad within tile (kq*4 .. +3)
    const int rA = tid >> 3;  // 0..31

    unsigned long long acc[4][6];
#pragma unroll
    for (int p = 0; p < 4; p++)
#pragma unroll
        for (int j = 0; j < 6; j++) acc[p][j] = 0ull;

    float4 px0, px1, px2, px3, pm0, pm1, pm2;

#define GLOAD(k0)                                                                   \
    px0 = *(const float4*)(X + (size_t)(i0 + rA) * DIM + (k0) + kq * 4);            \
    px1 = *(const float4*)(X + (size_t)(i0 + rA + 32) * DIM + (k0) + kq * 4);       \
    px2 = *(const float4*)(X + (size_t)(i0 + rA + 64) * DIM + (k0) + kq * 4);       \
    px3 = *(const float4*)(X + (size_t)(i0 + rA + 96) * DIM + (k0) + kq * 4);       \
    pm0 = *(const float4*)(g_mmean + (size_t)(rA) * DIM + (k0) + kq * 4);           \
    pm1 = *(const float4*)(g_mmean + (size_t)(rA + 32) * DIM + (k0) + kq * 4);      \
    pm2 = *(const float4*)(g_mmean + (size_t)(rA + 64) * DIM + (k0) + kq * 4);

#define GSTORE(dstbase)                                                             \
    {                                                                               \
        float* xd = (dstbase);                                                      \
        float* md = (dstbase) + KT * PADX;                                          \
        _Pragma("unroll") for (int v = 0; v < 4; v++) {                             \
            xd[(kq * 4 + v) * PADX + rA]      = ((float*)&px0)[v];                  \
            xd[(kq * 4 + v) * PADX + rA + 32] = ((float*)&px1)[v];                  \
            xd[(kq * 4 + v) * PADX + rA + 64] = ((float*)&px2)[v];                  \
            xd[(kq * 4 + v) * PADX + rA + 96] = ((float*)&px3)[v];                  \
            md[(kq * 4 + v) * PADM + rA]      = ((float*)&pm0)[v];                  \
            md[(kq * 4 + v) * PADM + rA + 32] = ((float*)&pm1)[v];                  \
            md[(kq * 4 + v) * PADM + rA + 64] = ((float*)&pm2)[v];                  \
        }                                                                           \
    }

    GLOAD(0);
    GSTORE(sm);
    __syncthreads();

    for (int t = 0; t < NTILES; t++) {
        if (t + 1 < NTILES) { GLOAD((t + 1) * KT); }

        const float* xb = sm + (t & 1) * STAGE_FLOATS;
        const float* mb = xb + KT * PADX;
#pragma unroll 8
        for (int k = 0; k < KT; k++) {
            const float* xrow = xb + k * PADX + iG * 8;
            ulonglong2 xa = *(const ulonglong2*)xrow;        // row pairs (0,1),(2,3)
            ulonglong2 xc = *(const ulonglong2*)(xrow + 4);  // row pairs (4,5),(6,7)
            const float2* mp = (const float2*)(mb + k * PADM + cG * 6);
            float2 mA = mp[0], mB = mp[1], mC = mp[2];
            unsigned long long mm0, mm1, mm2, mm3, mm4, mm5;
            PACK2(mm0, mA.x, mA.x); PACK2(mm1, mA.y, mA.y);
            PACK2(mm2, mB.x, mB.x); PACK2(mm3, mB.y, mB.y);
            PACK2(mm4, mC.x, mC.x); PACK2(mm5, mC.y, mC.y);
            FMA2(acc[0][0], xa.x, mm0, acc[0][0]); FMA2(acc[1][0], xa.y, mm0, acc[1][0]);
            FMA2(acc[2][0], xc.x, mm0, acc[2][0]); FMA2(acc[3][0], xc.y, mm0, acc[3][0]);
            FMA2(acc[0][1], xa.x, mm1, acc[0][1]); FMA2(acc[1][1], xa.y, mm1, acc[1][1]);
            FMA2(acc[2][1], xc.x, mm1, acc[2][1]); FMA2(acc[3][1], xc.y, mm1, acc[3][1]);
            FMA2(acc[0][2], xa.x, mm2, acc[0][2]); FMA2(acc[1][2], xa.y, mm2, acc[1][2]);
            FMA2(acc[2][2], xc.x, mm2, acc[2][2]); FMA2(acc[3][2], xc.y, mm2, acc[3][2]);
            FMA2(acc[0][3], xa.x, mm3, acc[0][3]); FMA2(acc[1][3], xa.y, mm3, acc[1][3]);
            FMA2(acc[2][3], xc.x, mm3, acc[2][3]); FMA2(acc[3][3], xc.y, mm3, acc[3][3]);
            FMA2(acc[0][4], xa.x, mm4, acc[0][4]); FMA2(acc[1][4], xa.y, mm4, acc[1][4]);
            FMA2(acc[2][4], xc.x, mm4, acc[2][4]); FMA2(acc[3][4], xc.y, mm4, acc[3][4]);
            FMA2(acc[0][5], xa.x, mm5, acc[0][5]); FMA2(acc[1][5], xa.y, mm5, acc[1][5]);
            FMA2(acc[2][5], xc.x, mm5, acc[2][5]); FMA2(acc[3][5], xc.y, mm5, acc[3][5]);
        }

        if (t + 1 < NTILES) {
            __syncthreads();
            GSTORE(sm + ((t + 1) & 1) * STAGE_FLOATS);
            __syncthreads();
        }
    }
    __syncthreads();

    // scores into smem (reused), padded row stride 97
    float* sc = sm;
#pragma unroll
    for (int j = 0; j < 6; j++) {
        int col = cG * 6 + j;
        float b = g_bias[col];
#pragma unroll
        for (int p = 0; p < 4; p++) {
            float lo, hi;
            UNPACK2(lo, hi, acc[p][j]);
            sc[(iG * 8 + 2 * p) * 97 + col]     = b - lo;
            sc[(iG * 8 + 2 * p + 1) * 97 + col] = b - hi;
        }
    }
    __syncthreads();

    if (tid < BM) {
        int gi = i0 + tid;
        const float* row = sc + tid * 97;
        float best = row[0];
        int bc = 0;
#pragma unroll 4
        for (int cc = 1; cc < NC; cc++) {
            float v = row[cc];
            if (v < best) { best = v; bc = cc; }
        }
        out[gi] = (float)bc;
        unsigned bal = __ballot_sync(0xffffffffu, bc == labels[gi]);
        if ((tid & 31) == 0) atomicAdd(&g_count, __popc(bal));
    }
}

// ---------------------------------------------------------------------------
// Kernel 3: finalize accuracy
// ---------------------------------------------------------------------------
__global__ void k_fin(float* __restrict__ out) {
    out[NI] = (float)g_count * (1.0f / NI);
}

// ---------------------------------------------------------------------------
// Kernel 4: sequential per-class memory update. One block/class, 256 threads.
// Bank in registers as f32x2; ONE barrier per step (double-buffered partials,
// redundant final reduction + slot decision on every thread, bn in registers).
// ---------------------------------------------------------------------------
__global__ void __launch_bounds__(256, 1)
k_update(const float* __restrict__ X, const int* __restrict__ labels,
         const float* __restrict__ mem, const int* __restrict__ mpos,
         float* __restrict__ out) {
    const int c = blockIdx.x, tid = threadIdx.x;
    const int w = tid >> 5, lane = tid & 31;

    __shared__ int   s_list[1024];
    __shared__ int   s_cnt;
    __shared__ int   s_wcnt[8];
    __shared__ float s_part[2][8][12];

    // ---- build ordered index list for class c ----
    const int SEG = NI / 8;
    const int base = w * SEG;
    const int4* lab4 = (const int4*)labels;
    int cnt = 0;
    for (int it = 0; it < SEG / 128; it++) {
        int4 v = lab4[(base >> 2) + it * 32 + lane];
        cnt += (v.x == c) + (v.y == c) + (v.z == c) + (v.w == c);
    }
#pragma unroll
    for (int o = 16; o; o >>= 1) cnt += __shfl_xor_sync(0xffffffffu, cnt, o);
    if (lane == 0) s_wcnt[w] = cnt;
    __syncthreads();
    if (tid == 0) {
        int t = 0;
        for (int ww = 0; ww < 8; ww++) { int v = s_wcnt[ww]; s_wcnt[ww] = t; t += v; }
        s_cnt = t;
    }
    __syncthreads();
    int off = s_wcnt[w];
    for (int it = 0; it < SEG / 128; it++) {
        int gidx = base + it * 128 + lane * 4;
        int4 v = lab4[gidx >> 2];
        int m0 = (v.x == c), m1 = (v.y == c), m2 = (v.z == c), m3 = (v.w == c);
        int nm = m0 + m1 + m2 + m3;
        int x = nm;
#pragma unroll
        for (int o = 1; o < 32; o <<= 1) {
            int y = __shfl_up_sync(0xffffffffu, x, o);
            if (lane >= o) x += y;
        }
        int p2 = off + x - nm;
        if (m0) { s_list[p2 < 1024 ? p2 : 1023] = gidx + 0; p2++; }
        if (m1) { s_list[p2 < 1024 ? p2 : 1023] = gidx + 1; p2++; }
        if (m2) { s_list[p2 < 1024 ? p2 : 1023] = gidx + 2; p2++; }
        if (m3) { s_list[p2 < 1024 ? p2 : 1023] = gidx + 3; p2++; }
        off += __shfl_sync(0xffffffffu, x, 31);
    }
    __syncthreads();

    // ---- bank into registers (f32x2 pairs); |b_j|^2 ----
    const ulonglong2* memU = (const ulonglong2*)mem + (size_t)c * BK * (DIM / 4);
    ulonglong2 br[BK][2];
    float part[11];
#pragma unroll
    for (int j = 0; j < BK; j++) {
        br[j][0] = memU[j * 512 + tid];
        br[j][1] = memU[j * 512 + 256 + tid];
        unsigned long long pa = 0ull;
        FMA2(pa, br[j][0].x, br[j][0].x, pa);
        FMA2(pa, br[j][0].y, br[j][0].y, pa);
        FMA2(pa, br[j][1].x, br[j][1].x, pa);
        FMA2(pa, br[j][1].y, br[j][1].y, pa);
        float lo, hi; UNPACK2(lo, hi, pa);
        part[j] = lo + hi;
    }
#pragma unroll
    for (int j = 0; j < BK; j++) {
        float v = part[j];
#pragma unroll
        for (int o = 16; o; o >>= 1) v += __shfl_xor_sync(0xffffffffu, v, o);
        part[j] = v;
    }
#pragma unroll
    for (int j = 0; j < BK; j++) if (lane == j) s_part[0][w][j] = part[j];
    if (lane == 10 || lane == 11) s_part[0][w][lane] = 0.f;
    __syncthreads();

    float bn[BK];
    {
        unsigned long long s0 = 0, s1 = 0, s2 = 0, s3 = 0, s4 = 0;
#pragma unroll
        for (int ww = 0; ww < 8; ww++) {
            const ulonglong2* r = (const ulonglong2*)s_part[0][ww];
            ulonglong2 q0 = r[0], q1 = r[1], q2 = r[2];
            ADD2(s0, s0, q0.x); ADD2(s1, s1, q0.y);
            ADD2(s2, s2, q1.x); ADD2(s3, s3, q1.y);
            ADD2(s4, s4, q2.x); (void)q2.y;
        }
        UNPACK2(bn[0], bn[1], s0); UNPACK2(bn[2], bn[3], s1);
        UNPACK2(bn[4], bn[5], s2); UNPACK2(bn[6], bn[7], s3);
        UNPACK2(bn[8], bn[9], s4);
    }

    // ---- sequential scan ----
    int p = mpos[c];
    const int n = s_cnt < 1024 ? s_cnt : 1024;
    const ulonglong2* XU = (const ulonglong2*)X;
    ulonglong2 xc0, xc1, xn0, xn1;
    xc0.x = xc0.y = xc1.x = xc1.y = 0ull;
    xn0 = xc0; xn1 = xc1;
    if (n > 0) {
        size_t rr = (size_t)s_list[0] * 512;
        xc0 = XU[rr + tid];
        xc1 = XU[rr + 256 + tid];
    }
    int buf = 1;
    for (int s = 0; s < n; s++) {
        if (s + 1 < n) {
            size_t rr = (size_t)s_list[s + 1] * 512;
            xn0 = XU[rr + tid];
            xn1 = XU[rr + 256 + tid];
        }
        float p10;
#pragma unroll
        for (int j = 0; j < BK; j++) {
            unsigned long long pa = 0ull;
            FMA2(pa, br[j][0].x, xc0.x, pa);
            FMA2(pa, br[j][0].y, xc0.y, pa);
            FMA2(pa, br[j][1].x, xc1.x, pa);
            FMA2(pa, br[j][1].y, xc1.y, pa);
            float lo, hi; UNPACK2(lo, hi, pa);
            part[j] = lo + hi;
        }
        {
            unsigned long long pa = 0ull;
            FMA2(pa, xc0.x, xc0.x, pa); FMA2(pa, xc0.y, xc0.y, pa);
            FMA2(pa, xc1.x, xc1.x, pa); FMA2(pa, xc1.y, xc1.y, pa);
            float lo, hi; UNPACK2(lo, hi, pa);
            p10 = lo + hi;
        }
#pragma unroll
        for (int j = 0; j < BK; j++) {
            float v = part[j];
#pragma unroll
            for (int o = 16; o; o >>= 1) v += __shfl_xor_sync(0xffffffffu, v, o);
            part[j] = v;
        }
#pragma unroll
        for (int o = 16; o; o >>= 1) p10 += __shfl_xor_sync(0xffffffffu, p10, o);
#pragma unroll
        for (int j = 0; j < BK; j++) if (lane == j) s_part[buf][w][j] = part[j];
        if (lane == 10) s_part[buf][w][10] = p10;
        if (lane == 11) s_part[buf][w][11] = 0.f;
        __syncthreads();

        float tot[12];
        {
            unsigned long long s0 = 0, s1 = 0, s2 = 0, s3 = 0, s4 = 0, s5 = 0;
#pragma unroll
            for (int ww = 0; ww < 8; ww++) {
                const ulonglong2* r = (const ulonglong2*)s_part[buf][ww];
                ulonglong2 q0 = r[0], q1 = r[1], q2 = r[2];
                ADD2(s0, s0, q0.x); ADD2(s1, s1, q0.y);
                ADD2(s2, s2, q1.x); ADD2(s3, s3, q1.y);
                ADD2(s4, s4, q2.x); ADD2(s5, s5, q2.y);
            }
            UNPACK2(tot[0], tot[1], s0); UNPACK2(tot[2], tot[3], s1);
            UNPACK2(tot[4], tot[5], s2); UNPACK2(tot[6], tot[7], s3);
            UNPACK2(tot[8], tot[9], s4); UNPACK2(tot[10], tot[11], s5);
        }
        float xx = tot[10];

        int slot;
        if (p < BK) {
            slot = p;
        } else {
            float d[BK];
#pragma unroll
            for (int j = 0; j < BK; j++) d[j] = fmaf(-2.f, tot[j], bn[j]);
            float mx = d[0];
#pragma unroll
            for (int j = 1; j < BK; j++) mx = fmaxf(mx, d[j]);
            slot = BK - 1;
#pragma unroll
            for (int j = BK - 1; j >= 0; j--) slot = (d[j] == mx) ? j : slot;
        }
#pragma unroll
        for (int j = 0; j < BK; j++) {
            bool h = (slot == j);
            br[j][0].x = h ? xc0.x : br[j][0].x;
            br[j][0].y = h ? xc0.y : br[j][0].y;
            br[j][1].x = h ? xc1.x : br[j][1].x;
            br[j][1].y = h ? xc1.y : br[j][1].y;
            bn[j] = h ? xx : bn[j];
        }
        if (p < BK) p++;
        xc0 = xn0; xc1 = xn1;
        buf ^= 1;
    }

    // ---- epilogue: write updated bank + pos (out+16385 only 4B-aligned) ----
    float* om = out + (NI + 1) + (size_t)c * BK * DIM;
#pragma unroll
    for (int j = 0; j < BK; j++) {
        float f0, f1, f2, f3;
        UNPACK2(f0, f1, br[j][0].x); UNPACK2(f2, f3, br[j][0].y);
        int d0 = j * DIM + tid * 4;
        om[d0 + 0] = f0; om[d0 + 1] = f1; om[d0 + 2] = f2; om[d0 + 3] = f3;
        UNPACK2(f0, f1, br[j][1].x); UNPACK2(f2, f3, br[j][1].y);
        int d1 = j * DIM + 1024 + tid * 4;
        om[d1 + 0] = f0; om[d1 + 1] = f1; om[d1 + 2] = f2; om[d1 + 3] = f3;
    }
    if (tid == 0) out[(NI + 1) + (size_t)NC * BK * DIM + c] = (float)p;
}

// ---------------------------------------------------------------------------
extern "C" void kernel_launch(void* const* d_in, const int* in_sizes, int n_in,
                              void* d_out, int out_size) {
    const float* X      = (const float*)d_in[0];
    const int*   labels = (const int*)d_in[1];
    const float* mem    = (const float*)d_in[2];
    const int*   mpos   = (const int*)d_in[3];
    float* out = (float*)d_out;

    static cudaStream_t s2 = nullptr;
    static cudaEvent_t evA = nullptr, evB = nullptr;
    if (s2 == nullptr) {
        cudaStreamCreateWithFlags(&s2, cudaStreamNonBlocking);
        cudaEventCreateWithFlags(&evA, cudaEventDisableTiming);
        cudaEventCreateWithFlags(&evB, cudaEventDisableTiming);
        cudaFuncSetAttribute(k_gemm, cudaFuncAttributeMaxDynamicSharedMemorySize,
                             SMEM_GEMM_BYTES);
    }

    // fork: k_update (independent) runs concurrently with mean+gemm+fin
    cudaEventRecord(evA, 0);
    cudaStreamWaitEvent(s2, evA, 0);
    k_update<<<NC, 256, 0, s2>>>(X, labels, mem, mpos, out);
    cudaEventRecord(evB, s2);

    k_mean<<<NCP, 256>>>(mem);
    k_gemm<<<NI / BM, 256, SMEM_GEMM_BYTES>>>(X, labels, out);
    k_fin<<<1, 1>>>(out);

    cudaStreamWaitEvent(0, evB, 0);
}